// round 9
// baseline (speedup 1.0000x reference)
#include <cuda_runtime.h>

// out[row, t] = x[row, t - s]  if 0 <= t - s < T else 0
// rows = 256, T = 160000 (T % 4 == 0), s = shifts[row] - max_shift in [-16000, 16000]
//
// Persistent grid-stride kernel: launch ~1 wave of CTAs; each CTA loops over
// tiles. Eliminates the ~8 wave transitions of the 10240-CTA launch (each
// transition drains the memory pipeline). Tile body = best-known R3 config:
// VEC=4 float4 words/thread strided by blockDim, all loads front-batched
// (__ldcs streaming), stores __stcs, interior tiles skip predication.

#define VEC 4
#define THREADS 256
#define WPB (VEC * THREADS)   // 1024 float4 words = 4096 floats per tile

__global__ void __launch_bounds__(THREADS)
random_shift_kernel(const float* __restrict__ x,
                    const int* __restrict__ shifts,
                    float4* __restrict__ out4,
                    int T, int max_shift, int ntiles, int tiles_per_row) {
    const int T4 = T >> 2;

    for (int tile = blockIdx.x; tile < ntiles; tile += gridDim.x) {
        const int row = tile / tiles_per_row;
        const int tile0 = (tile - row * tiles_per_row) * WPB;   // first word
        const int s = shifts[row] - max_shift;

        const size_t ebase = (size_t)row * (size_t)T;
        const size_t wbase = (size_t)row * (size_t)T4;
        const float* __restrict__ xr = x + ebase;

        const int src_lo = 4 * tile0 - s;
        const int src_hi = 4 * (tile0 + WPB) - s;
        const bool interior = (src_lo >= 0) && (src_hi <= T) && (tile0 + WPB <= T4);

        float4 v[VEC];

        if (interior) {
#pragma unroll
            for (int k = 0; k < VEC; ++k) {
                const int u = 4 * (tile0 + (int)threadIdx.x + k * THREADS) - s;
                v[k].x = __ldcs(xr + u);
                v[k].y = __ldcs(xr + u + 1);
                v[k].z = __ldcs(xr + u + 2);
                v[k].w = __ldcs(xr + u + 3);
            }
#pragma unroll
            for (int k = 0; k < VEC; ++k) {
                const int w = tile0 + threadIdx.x + k * THREADS;
                __stcs(out4 + wbase + w, v[k]);
            }
        } else {
#pragma unroll
            for (int k = 0; k < VEC; ++k) {
                const int w = tile0 + threadIdx.x + k * THREADS;
                const int u = 4 * w - s;
                float t0 = 0.f, t1 = 0.f, t2 = 0.f, t3 = 0.f;
                if (w < T4) {
                    if (u >= 0 && u + 3 < T) {
                        t0 = __ldcs(xr + u);
                        t1 = __ldcs(xr + u + 1);
                        t2 = __ldcs(xr + u + 2);
                        t3 = __ldcs(xr + u + 3);
                    } else {
                        if (u >= 0     && u < T)     t0 = __ldcs(xr + u);
                        if (u + 1 >= 0 && u + 1 < T) t1 = __ldcs(xr + u + 1);
                        if (u + 2 >= 0 && u + 2 < T) t2 = __ldcs(xr + u + 2);
                        if (u + 3 >= 0 && u + 3 < T) t3 = __ldcs(xr + u + 3);
                    }
                }
                v[k] = make_float4(t0, t1, t2, t3);
            }
#pragma unroll
            for (int k = 0; k < VEC; ++k) {
                const int w = tile0 + threadIdx.x + k * THREADS;
                if (w < T4)
                    __stcs(out4 + wbase + w, v[k]);
            }
        }
    }
}

extern "C" void kernel_launch(void* const* d_in, const int* in_sizes, int n_in,
                              void* d_out, int out_size) {
    const float* x      = (const float*)d_in[0];
    const int*   shifts = (const int*)d_in[1];
    float4*      out4   = (float4*)d_out;

    const int rows = in_sizes[1];            // B*M = 256
    const int T    = in_sizes[0] / rows;     // 160000
    const int T4   = T / 4;                  // 40000
    const int max_shift = T / 10;            // 16000

    const int tiles_per_row = (T4 + WPB - 1) / WPB;   // 40
    const int ntiles = tiles_per_row * rows;          // 10240

    // ~1 full wave: 152 SMs x 8 CTAs (256 thr, 32 regs -> occ 8)
    int nblocks = 152 * 8;
    if (nblocks > ntiles) nblocks = ntiles;

    random_shift_kernel<<<nblocks, THREADS>>>(x, shifts, out4, T, max_shift,
                                              ntiles, tiles_per_row);
}

// round 10
// speedup vs baseline: 1.0023x; 1.0023x over previous
#include <cuda_runtime.h>

// out[row, t] = x[row, t - s]  if 0 <= t - s < T else 0
// rows = 256, T = 160000 (T % 8 == 0), s = shifts[row] - max_shift in [-16000, 16000]
//
// R3 config (front-batched streaming scalar loads, interior fast path, full
// grid) with the store side upgraded to aligned 256-bit st.global.v8.b32:
// each thread owns 2 adjacent float4-word pairs -> 2 STG.256 instead of
// 4 STG.128, halving write-request count. Reads must remain scalar LDG.32
// (source is row-misaligned; vector loads require natural alignment).

#define PAIRS 2               // 32-byte octets per thread
#define THREADS 256
#define WPB (PAIRS * 2 * THREADS)   // 1024 float4 words = 4096 floats per tile

__device__ __forceinline__ void st256_cs(float4* p, float4 a, float4 b) {
    asm volatile("st.global.cs.v8.b32 [%0], {%1,%2,%3,%4,%5,%6,%7,%8};"
                 :: "l"(p),
                    "f"(a.x), "f"(a.y), "f"(a.z), "f"(a.w),
                    "f"(b.x), "f"(b.y), "f"(b.z), "f"(b.w)
                 : "memory");
}

__global__ void __launch_bounds__(THREADS)
random_shift_kernel(const float* __restrict__ x,
                    const int* __restrict__ shifts,
                    float4* __restrict__ out4,
                    int T, int max_shift) {
    const int row = blockIdx.y;
    const int s = shifts[row] - max_shift;

    const int T4 = T >> 2;
    const int tile0 = blockIdx.x * WPB;                 // first word of tile
    const size_t ebase = (size_t)row * (size_t)T;
    const size_t wbase = (size_t)row * (size_t)T4;
    const float* __restrict__ xr = x + ebase;

    const int src_lo = 4 * tile0 - s;
    const int src_hi = 4 * (tile0 + WPB) - s;
    const bool interior = (src_lo >= 0) && (src_hi <= T) && (tile0 + WPB <= T4);

    float4 v[2 * PAIRS];

    if (interior) {
#pragma unroll
        for (int p = 0; p < PAIRS; ++p) {
            // this thread's octet p starts at word: tile0 + 2*(tid + p*THREADS)
            const int w0 = tile0 + 2 * ((int)threadIdx.x + p * THREADS);
            const int u  = 4 * w0 - s;                  // 8 consecutive source elems
#pragma unroll
            for (int e = 0; e < 8; ++e)
                ((float*)&v[2 * p])[e] = __ldcs(xr + u + e);
        }
#pragma unroll
        for (int p = 0; p < PAIRS; ++p) {
            const int w0 = tile0 + 2 * ((int)threadIdx.x + p * THREADS);
            st256_cs(out4 + wbase + w0, v[2 * p], v[2 * p + 1]);   // 32B-aligned
        }
    } else {
#pragma unroll
        for (int p = 0; p < PAIRS; ++p) {
            const int w0 = tile0 + 2 * ((int)threadIdx.x + p * THREADS);
            const int u  = 4 * w0 - s;
            float f[8];
#pragma unroll
            for (int e = 0; e < 8; ++e) {
                const int uu = u + e;
                f[e] = (w0 < T4 && uu >= 0 && uu < T) ? __ldcs(xr + uu) : 0.0f;
            }
            v[2 * p]     = make_float4(f[0], f[1], f[2], f[3]);
            v[2 * p + 1] = make_float4(f[4], f[5], f[6], f[7]);
        }
#pragma unroll
        for (int p = 0; p < PAIRS; ++p) {
            const int w0 = tile0 + 2 * ((int)threadIdx.x + p * THREADS);
            if (w0 + 1 < T4)
                st256_cs(out4 + wbase + w0, v[2 * p], v[2 * p + 1]);
            else if (w0 < T4)
                __stcs(out4 + wbase + w0, v[2 * p]);
        }
    }
}

extern "C" void kernel_launch(void* const* d_in, const int* in_sizes, int n_in,
                              void* d_out, int out_size) {
    const float* x      = (const float*)d_in[0];
    const int*   shifts = (const int*)d_in[1];
    float4*      out4   = (float4*)d_out;

    const int rows = in_sizes[1];            // B*M = 256
    const int T    = in_sizes[0] / rows;     // 160000
    const int T4   = T / 4;                  // 40000
    const int max_shift = T / 10;            // 16000

    dim3 grid((T4 + WPB - 1) / WPB, rows);   // (40, 256)
    random_shift_kernel<<<grid, THREADS>>>(x, shifts, out4, T, max_shift);
}

// round 11
// speedup vs baseline: 1.0568x; 1.0543x over previous
#include <cuda_runtime.h>

// out[row, t] = x[row, t - s]  if 0 <= t - s < T else 0
// rows = 256, T = 160000 (T % 4 == 0), s = shifts[row] - max_shift in [-16000, 16000]
//
// Best-known structure (R3): per-row block tiles, VEC=4 float4 words per
// thread strided by blockDim, all loads front-batched before stores (MLP=4),
// interior tiles skip all predication. This round: default cache policy on
// BOTH loads and stores (last untested policy cell; .cs gave no benefit and
// the evict-first store path may drain slightly worse than default).

#define VEC 4
#define THREADS 256
#define WPB (VEC * THREADS)   // 1024 float4 words = 4096 floats per tile

__global__ void __launch_bounds__(THREADS)
random_shift_kernel(const float* __restrict__ x,
                    const int* __restrict__ shifts,
                    float4* __restrict__ out4,
                    int T, int max_shift) {
    const int row = blockIdx.y;
    const int s = shifts[row] - max_shift;

    const int T4 = T >> 2;
    const int tile0 = blockIdx.x * WPB;
    const size_t ebase = (size_t)row * (size_t)T;
    const size_t wbase = (size_t)row * (size_t)T4;
    const float* __restrict__ xr = x + ebase;

    const int src_lo = 4 * tile0 - s;
    const int src_hi = src_lo + 4 * WPB;
    const bool interior = (src_lo >= 0) && (src_hi <= T) && (tile0 + WPB <= T4);

    float4 v[VEC];

    if (interior) {
        const int u0 = 4 * (tile0 + (int)threadIdx.x) - s;
#pragma unroll
        for (int k = 0; k < VEC; ++k) {
            const int u = u0 + 4 * k * THREADS;
            v[k].x = __ldg(xr + u);
            v[k].y = __ldg(xr + u + 1);
            v[k].z = __ldg(xr + u + 2);
            v[k].w = __ldg(xr + u + 3);
        }
        const size_t o0 = wbase + tile0 + threadIdx.x;
#pragma unroll
        for (int k = 0; k < VEC; ++k)
            out4[o0 + k * THREADS] = v[k];
    } else {
#pragma unroll
        for (int k = 0; k < VEC; ++k) {
            const int w = tile0 + threadIdx.x + k * THREADS;
            const int u = 4 * w - s;
            float t0 = 0.f, t1 = 0.f, t2 = 0.f, t3 = 0.f;
            if (w < T4) {
                if (u >= 0 && u + 3 < T) {
                    t0 = __ldg(xr + u);
                    t1 = __ldg(xr + u + 1);
                    t2 = __ldg(xr + u + 2);
                    t3 = __ldg(xr + u + 3);
                } else {
                    if (u >= 0     && u < T)     t0 = __ldg(xr + u);
                    if (u + 1 >= 0 && u + 1 < T) t1 = __ldg(xr + u + 1);
                    if (u + 2 >= 0 && u + 2 < T) t2 = __ldg(xr + u + 2);
                    if (u + 3 >= 0 && u + 3 < T) t3 = __ldg(xr + u + 3);
                }
            }
            v[k] = make_float4(t0, t1, t2, t3);
        }
#pragma unroll
        for (int k = 0; k < VEC; ++k) {
            const int w = tile0 + threadIdx.x + k * THREADS;
            if (w < T4)
                out4[wbase + w] = v[k];
        }
    }
}

extern "C" void kernel_launch(void* const* d_in, const int* in_sizes, int n_in,
                              void* d_out, int out_size) {
    const float* x      = (const float*)d_in[0];
    const int*   shifts = (const int*)d_in[1];
    float4*      out4   = (float4*)d_out;

    const int rows = in_sizes[1];            // B*M = 256
    const int T    = in_sizes[0] / rows;     // 160000
    const int T4   = T / 4;                  // 40000
    const int max_shift = T / 10;            // 16000

    dim3 grid((T4 + WPB - 1) / WPB, rows);   // (40, 256)
    random_shift_kernel<<<grid, THREADS>>>(x, shifts, out4, T, max_shift);
}

// round 12
// speedup vs baseline: 1.0718x; 1.0142x over previous
#include <cuda_runtime.h>

// out[row, t] = x[row, t - s]  if 0 <= t - s < T else 0
// rows = 256, T = 160000 (T % 4 == 0), s = shifts[row] - max_shift in [-16000, 16000]
//
// FINAL (R3-optimal) configuration, locked in after exhausting the experiment
// matrix {alignment, vector width 32/128/256b, MLP 1/4/8, cache policies,
// L2 residency splits, persistent grid}: all configs plateau at ~74% DRAM
// (~5.85 TB/s) moving ~265 MB/iter — the mixed read+write HBM turnaround
// ceiling. This config is the measured optimum:
//  - per-row block tiles of 4096 floats; VEC=4 float4 words per thread,
//    strided by blockDim (every instruction fully coalesced)
//  - all loads front-batched before any store (MLP=4 words/thread)
//  - streaming cache hints on both sides (__ldcs/__stcs, zero-reuse data)
//  - interior tiles (~90%) skip all bounds predication
//  - full 10240-CTA launch (grid-stride/persistent variants regress)

#define VEC 4
#define THREADS 256
#define WPB (VEC * THREADS)   // 1024 float4 words = 4096 floats per tile

__global__ void __launch_bounds__(THREADS)
random_shift_kernel(const float* __restrict__ x,
                    const int* __restrict__ shifts,
                    float4* __restrict__ out4,
                    int T, int max_shift) {
    const int row = blockIdx.y;
    const int s = shifts[row] - max_shift;

    const int T4 = T >> 2;
    const int tile0 = blockIdx.x * WPB;                    // first word of tile
    const size_t ebase = (size_t)row * (size_t)T;          // element base
    const size_t wbase = (size_t)row * (size_t)T4;         // word base
    const float* __restrict__ xr = x + ebase;

    // tile source element range: [4*tile0 - s, 4*(tile0+WPB) - s)
    const int src_lo = 4 * tile0 - s;
    const int src_hi = 4 * (tile0 + WPB) - s;
    const bool interior = (src_lo >= 0) && (src_hi <= T) && (tile0 + WPB <= T4);

    float4 v[VEC];

    if (interior) {
#pragma unroll
        for (int k = 0; k < VEC; ++k) {
            const int u = 4 * (tile0 + (int)threadIdx.x + k * THREADS) - s;
            v[k].x = __ldcs(xr + u);
            v[k].y = __ldcs(xr + u + 1);
            v[k].z = __ldcs(xr + u + 2);
            v[k].w = __ldcs(xr + u + 3);
        }
#pragma unroll
        for (int k = 0; k < VEC; ++k) {
            const int w = tile0 + threadIdx.x + k * THREADS;
            __stcs(out4 + wbase + w, v[k]);
        }
    } else {
#pragma unroll
        for (int k = 0; k < VEC; ++k) {
            const int w = tile0 + threadIdx.x + k * THREADS;
            const int u = 4 * w - s;
            float t0 = 0.f, t1 = 0.f, t2 = 0.f, t3 = 0.f;
            if (w < T4) {
                if (u >= 0 && u + 3 < T) {
                    t0 = __ldcs(xr + u);
                    t1 = __ldcs(xr + u + 1);
                    t2 = __ldcs(xr + u + 2);
                    t3 = __ldcs(xr + u + 3);
                } else {
                    if (u >= 0     && u < T)     t0 = __ldcs(xr + u);
                    if (u + 1 >= 0 && u + 1 < T) t1 = __ldcs(xr + u + 1);
                    if (u + 2 >= 0 && u + 2 < T) t2 = __ldcs(xr + u + 2);
                    if (u + 3 >= 0 && u + 3 < T) t3 = __ldcs(xr + u + 3);
                }
            }
            v[k] = make_float4(t0, t1, t2, t3);
        }
#pragma unroll
        for (int k = 0; k < VEC; ++k) {
            const int w = tile0 + threadIdx.x + k * THREADS;
            if (w < T4)
                __stcs(out4 + wbase + w, v[k]);
        }
    }
}

extern "C" void kernel_launch(void* const* d_in, const int* in_sizes, int n_in,
                              void* d_out, int out_size) {
    const float* x      = (const float*)d_in[0];
    const int*   shifts = (const int*)d_in[1];
    float4*      out4   = (float4*)d_out;

    const int rows = in_sizes[1];            // B*M = 256
    const int T    = in_sizes[0] / rows;     // 160000
    const int T4   = T / 4;                  // 40000
    const int max_shift = T / 10;            // 16000

    dim3 grid((T4 + WPB - 1) / WPB, rows);   // (40, 256)
    random_shift_kernel<<<grid, THREADS>>>(x, shifts, out4, T, max_shift);
}